// round 4
// baseline (speedup 1.0000x reference)
#include <cuda_runtime.h>
#include <cuda_bf16.h>
#include <mma.h>
#include <cuda_pipeline.h>
#include <math.h>

using namespace nvcuda;

// Problem dims
#define MROWS 16384            // B*S
#define DDIM  2048             // D
#define MSZ   ((size_t)MROWS * DDIM)
#define WSZ   ((size_t)DDIM * DDIM)

// ---------------- device scratch (allocation-free rule: __device__ globals) ----
__device__ __nv_bfloat16 g_Ah[MSZ];        // activation split hi  (X, then X1)
__device__ __nv_bfloat16 g_Al[MSZ];        // activation split lo
__device__ __nv_bfloat16 g_Hh[MSZ];        // gelu output split hi
__device__ __nv_bfloat16 g_Hl[MSZ];        // gelu output split lo
__device__ __nv_bfloat16 g_Wh[5 * WSZ];    // weight splits hi (Wq,Wk,Wv,W1,W2)
__device__ __nv_bfloat16 g_Wl[5 * WSZ];    // weight splits lo
__device__ float g_Q [MSZ];                // Q, later reused as y2
__device__ float g_K [MSZ];
__device__ float g_V [MSZ];
__device__ float g_X1[MSZ];

// ---------------- split fp32 -> (bf16 hi, bf16 lo) -----------------------------
__global__ void split_kernel(const float* __restrict__ x,
                             __nv_bfloat16* __restrict__ hi,
                             __nv_bfloat16* __restrict__ lo, int n)
{
    int i = blockIdx.x * blockDim.x + threadIdx.x;
    if (i < n) {
        float v = x[i];
        __nv_bfloat16 h = __float2bfloat16(v);
        hi[i] = h;
        lo[i] = __float2bfloat16(v - __bfloat162float(h));
    }
}

// ---------------- bf16x3 GEMM: C[M,N] = (Ah+Al)(Bh+Bl) approx, fp32 accum -------
// Logical K3 = 3*K: seg0 = Ah*Bh, seg1 = Al*Bh, seg2 = Ah*Bl.
// EPI 0: C = acc + bias (fp32 out)
// EPI 1: g = gelu_exact(acc + bias); Oh/Ol = bf16 split of g
constexpr int BM = 128, BN = 128, BK = 32;

template<int EPI>
__global__ void __launch_bounds__(256)
gemm_bf16x3(const __nv_bfloat16* __restrict__ Ah, const __nv_bfloat16* __restrict__ Al,
            const __nv_bfloat16* __restrict__ Bh, const __nv_bfloat16* __restrict__ Bl,
            const float* __restrict__ bias,
            float* __restrict__ C,
            __nv_bfloat16* __restrict__ Oh, __nv_bfloat16* __restrict__ Ol)
{
    constexpr int K = DDIM, N = DDIM;
    __shared__ __align__(16) __nv_bfloat16 sA[2][BM][BK + 8];
    __shared__ __align__(16) __nv_bfloat16 sB[2][BK][BN + 8];
    __shared__ __align__(16) float sEpi[8][256];

    const int tid  = threadIdx.x;
    const int warp = tid >> 5, lane = tid & 31;
    const int wm = warp & 1;          // 0..1  -> 64-row slab
    const int wn = warp >> 1;         // 0..3  -> 32-col slab
    const int m0 = blockIdx.y * BM, n0 = blockIdx.x * BN;

    wmma::fragment<wmma::accumulator, 16, 16, 16, float> acc[4][2];
    #pragma unroll
    for (int i = 0; i < 4; i++)
        #pragma unroll
        for (int j = 0; j < 2; j++) wmma::fill_fragment(acc[i][j], 0.0f);

    auto load_tiles = [&](int b, int kt) {
        int seg = (kt >= 2 * K) ? 2 : ((kt >= K) ? 1 : 0);
        int kk  = kt - seg * K;
        const __nv_bfloat16* Ap = (seg == 1) ? Al : Ah;
        const __nv_bfloat16* Bp = (seg == 2) ? Bl : Bh;
        #pragma unroll
        for (int r = 0; r < 2; r++) {
            int idx = tid + r * 256;          // 0..511  (128x32 / 8)
            int row = idx >> 2;
            int c   = (idx & 3) * 8;
            __pipeline_memcpy_async(&sA[b][row][c],
                                    &Ap[(size_t)(m0 + row) * K + kk + c], 16);
        }
        #pragma unroll
        for (int r = 0; r < 2; r++) {
            int idx = tid + r * 256;          // 0..511  (32x128 / 8)
            int row = idx >> 4;
            int c   = (idx & 15) * 8;
            __pipeline_memcpy_async(&sB[b][row][c],
                                    &Bp[(size_t)(kk + row) * N + n0 + c], 16);
        }
        __pipeline_commit();
    };

    const int nIter = (3 * K) / BK;   // 192
    load_tiles(0, 0);
    for (int it = 0; it < nIter; ++it) {
        int cur = it & 1;
        __pipeline_wait_prior(0);
        __syncthreads();
        if (it + 1 < nIter) load_tiles(cur ^ 1, (it + 1) * BK);
        #pragma unroll
        for (int k2 = 0; k2 < BK; k2 += 16) {
            wmma::fragment<wmma::matrix_a, 16, 16, 16, __nv_bfloat16, wmma::row_major> af[4];
            wmma::fragment<wmma::matrix_b, 16, 16, 16, __nv_bfloat16, wmma::row_major> bfr[2];
            #pragma unroll
            for (int i = 0; i < 4; i++)
                wmma::load_matrix_sync(af[i], &sA[cur][wm * 64 + i * 16][k2], BK + 8);
            #pragma unroll
            for (int j = 0; j < 2; j++)
                wmma::load_matrix_sync(bfr[j], &sB[cur][k2][wn * 32 + j * 16], BN + 8);
            #pragma unroll
            for (int i = 0; i < 4; i++)
                #pragma unroll
                for (int j = 0; j < 2; j++)
                    wmma::mma_sync(acc[i][j], af[i], bfr[j], acc[i][j]);
        }
        __syncthreads();
    }

    // epilogue via warp-private smem staging
    float* buf = sEpi[warp];
    #pragma unroll
    for (int i = 0; i < 4; i++) {
        #pragma unroll
        for (int j = 0; j < 2; j++) {
            wmma::store_matrix_sync(buf, acc[i][j], 16, wmma::mem_row_major);
            __syncwarp();
            const int gr = m0 + wm * 64 + i * 16;
            const int gc = n0 + wn * 32 + j * 16;
            const int r  = lane >> 1, ch = (lane & 1) * 8;
            #pragma unroll
            for (int e = 0; e < 8; e++) {
                int cc = ch + e;
                float v = buf[r * 16 + cc] + bias[gc + cc];
                size_t o = (size_t)(gr + r) * N + gc + cc;
                if (EPI == 0) {
                    C[o] = v;
                } else {
                    float gl = v * normcdff(v);   // exact GELU: x * Phi(x)
                    __nv_bfloat16 hh = __float2bfloat16(gl);
                    Oh[o] = hh;
                    Ol[o] = __float2bfloat16(gl - __bfloat162float(hh));
                }
            }
            __syncwarp();
        }
    }
}

// ---------------- per-token head-attention + residual + LN1 --------------------
// att[h,t] = softmax_t( q_h . k_t / sqrt(128) );  y[h,:] = sum_t att[h,t] v[t,:]
// X1 = LN(X + y) * g1 + beta1 ; also emit bf16 split of X1.
__global__ void __launch_bounds__(128)
attn_ln1_kernel(const float* __restrict__ Q, const float* __restrict__ Kk,
                const float* __restrict__ V, const float* __restrict__ X,
                const float* __restrict__ g1, const float* __restrict__ be1,
                float* __restrict__ X1,
                __nv_bfloat16* __restrict__ Oh, __nv_bfloat16* __restrict__ Ol)
{
    __shared__ float sq[16 * 129], sk[16 * 129], sv[16 * 129];  // padded rows
    __shared__ float satt[16][16];
    __shared__ float red[8];

    const int t = blockIdx.x, tid = threadIdx.x;
    const size_t base = (size_t)t * DDIM;

    for (int i = tid; i < DDIM; i += 128) {
        int h = i >> 7, d = i & 127, o = h * 129 + d;
        sq[o] = Q[base + i]; sk[o] = Kk[base + i]; sv[o] = V[base + i];
    }
    __syncthreads();

    for (int p = tid; p < 256; p += 128) {
        int h = p >> 4, tt = p & 15;
        const float* qp = sq + h * 129;
        const float* kp = sk + tt * 129;
        float s = 0.f;
        #pragma unroll
        for (int d = 0; d < 128; d++) s += qp[d] * kp[d];
        satt[h][tt] = s * 0.08838834764831845f;   // 1/sqrt(128)
    }
    __syncthreads();

    if (tid < 16) {
        float mx = -1e30f;
        #pragma unroll
        for (int j = 0; j < 16; j++) mx = fmaxf(mx, satt[tid][j]);
        float sum = 0.f;
        #pragma unroll
        for (int j = 0; j < 16; j++) { float e = expf(satt[tid][j] - mx); satt[tid][j] = e; sum += e; }
        float inv = 1.f / sum;
        #pragma unroll
        for (int j = 0; j < 16; j++) satt[tid][j] *= inv;
    }
    __syncthreads();

    float xp[16], ls = 0.f, lq = 0.f;
    #pragma unroll
    for (int i = 0; i < 16; i++) {
        int o = tid + i * 128, h = o >> 7, d = o & 127;
        float y = 0.f;
        #pragma unroll
        for (int tt = 0; tt < 16; tt++) y += satt[h][tt] * sv[tt * 129 + d];
        float xv = X[base + o] + y;
        xp[i] = xv; ls += xv; lq += xv * xv;
    }
    #pragma unroll
    for (int off = 16; off; off >>= 1) {
        ls += __shfl_xor_sync(0xffffffffu, ls, off);
        lq += __shfl_xor_sync(0xffffffffu, lq, off);
    }
    if ((tid & 31) == 0) { red[tid >> 5] = ls; red[4 + (tid >> 5)] = lq; }
    __syncthreads();
    float S  = red[0] + red[1] + red[2] + red[3];
    float Qs = red[4] + red[5] + red[6] + red[7];
    float mean = S * (1.0f / DDIM);
    float var  = Qs * (1.0f / DDIM) - mean * mean;
    float inv  = rsqrtf(var + 1e-5f);
    #pragma unroll
    for (int i = 0; i < 16; i++) {
        int o = tid + i * 128;
        float v = (xp[i] - mean) * inv * g1[o] + be1[o];
        X1[base + o] = v;
        __nv_bfloat16 hh = __float2bfloat16(v);
        Oh[base + o] = hh;
        Ol[base + o] = __float2bfloat16(v - __bfloat162float(hh));
    }
}

// ---------------- out = LN(A + B) * g + beta -----------------------------------
__global__ void __launch_bounds__(256)
add_ln_kernel(const float* __restrict__ A, const float* __restrict__ Bv,
              const float* __restrict__ g, const float* __restrict__ be,
              float* __restrict__ out)
{
    __shared__ float red[16];
    const int t = blockIdx.x, tid = threadIdx.x;
    const size_t base = (size_t)t * DDIM;
    float xp[8], ls = 0.f, lq = 0.f;
    #pragma unroll
    for (int i = 0; i < 8; i++) {
        int o = tid + i * 256;
        float xv = A[base + o] + Bv[base + o];
        xp[i] = xv; ls += xv; lq += xv * xv;
    }
    #pragma unroll
    for (int off = 16; off; off >>= 1) {
        ls += __shfl_xor_sync(0xffffffffu, ls, off);
        lq += __shfl_xor_sync(0xffffffffu, lq, off);
    }
    if ((tid & 31) == 0) { red[tid >> 5] = ls; red[8 + (tid >> 5)] = lq; }
    __syncthreads();
    float S = 0.f, Qs = 0.f;
    #pragma unroll
    for (int w = 0; w < 8; w++) { S += red[w]; Qs += red[8 + w]; }
    float mean = S * (1.0f / DDIM);
    float var  = Qs * (1.0f / DDIM) - mean * mean;
    float inv  = rsqrtf(var + 1e-5f);
    #pragma unroll
    for (int i = 0; i < 8; i++) {
        int o = tid + i * 256;
        out[base + o] = (xp[i] - mean) * inv * g[o] + be[o];
    }
}

// ---------------- host orchestration -------------------------------------------
extern "C" void kernel_launch(void* const* d_in, const int* in_sizes, int n_in,
                              void* d_out, int out_size)
{
    const float* X     = (const float*)d_in[0];
    const float* Wq    = (const float*)d_in[1];
    const float* bq    = (const float*)d_in[2];
    const float* Wk    = (const float*)d_in[3];
    const float* bk    = (const float*)d_in[4];
    const float* Wv    = (const float*)d_in[5];
    const float* bv    = (const float*)d_in[6];
    const float* g1    = (const float*)d_in[7];
    const float* beta1 = (const float*)d_in[8];
    const float* W1    = (const float*)d_in[9];
    const float* b1    = (const float*)d_in[10];
    const float* W2    = (const float*)d_in[11];
    const float* b2    = (const float*)d_in[12];
    const float* g2    = (const float*)d_in[13];
    const float* beta2 = (const float*)d_in[14];
    float* out = (float*)d_out;

    __nv_bfloat16 *Ah, *Al, *Hh, *Hl, *Wh, *Wl;
    float *Q, *K, *V, *X1;
    cudaGetSymbolAddress((void**)&Ah, g_Ah);
    cudaGetSymbolAddress((void**)&Al, g_Al);
    cudaGetSymbolAddress((void**)&Hh, g_Hh);
    cudaGetSymbolAddress((void**)&Hl, g_Hl);
    cudaGetSymbolAddress((void**)&Wh, g_Wh);
    cudaGetSymbolAddress((void**)&Wl, g_Wl);
    cudaGetSymbolAddress((void**)&Q,  g_Q);
    cudaGetSymbolAddress((void**)&K,  g_K);
    cudaGetSymbolAddress((void**)&V,  g_V);
    cudaGetSymbolAddress((void**)&X1, g_X1);

    const int nA = MROWS * DDIM;
    const int nW = DDIM * DDIM;
    split_kernel<<<(nA + 255) / 256, 256>>>(X,  Ah, Al, nA);
    split_kernel<<<(nW + 255) / 256, 256>>>(Wq, Wh + 0 * WSZ, Wl + 0 * WSZ, nW);
    split_kernel<<<(nW + 255) / 256, 256>>>(Wk, Wh + 1 * WSZ, Wl + 1 * WSZ, nW);
    split_kernel<<<(nW + 255) / 256, 256>>>(Wv, Wh + 2 * WSZ, Wl + 2 * WSZ, nW);
    split_kernel<<<(nW + 255) / 256, 256>>>(W1, Wh + 3 * WSZ, Wl + 3 * WSZ, nW);
    split_kernel<<<(nW + 255) / 256, 256>>>(W2, Wh + 4 * WSZ, Wl + 4 * WSZ, nW);

    dim3 gg(DDIM / BN, MROWS / BM);   // (16, 128)
    gemm_bf16x3<0><<<gg, 256>>>(Ah, Al, Wh + 0 * WSZ, Wl + 0 * WSZ, bq, Q,  nullptr, nullptr);
    gemm_bf16x3<0><<<gg, 256>>>(Ah, Al, Wh + 1 * WSZ, Wl + 1 * WSZ, bk, K,  nullptr, nullptr);
    gemm_bf16x3<0><<<gg, 256>>>(Ah, Al, Wh + 2 * WSZ, Wl + 2 * WSZ, bv, V,  nullptr, nullptr);

    attn_ln1_kernel<<<MROWS, 128>>>(Q, K, V, X, g1, beta1, X1, Ah, Al);

    gemm_bf16x3<1><<<gg, 256>>>(Ah, Al, Wh + 3 * WSZ, Wl + 3 * WSZ, b1, nullptr, Hh, Hl);
    gemm_bf16x3<0><<<gg, 256>>>(Hh, Hl, Wh + 4 * WSZ, Wl + 4 * WSZ, b2, Q,  nullptr, nullptr);

    add_ln_kernel<<<MROWS, 256>>>(X1, Q, g2, beta2, out);
}

// round 7
// speedup vs baseline: 1.0327x; 1.0327x over previous
#include <cuda_runtime.h>
#include <cuda_bf16.h>
#include <mma.h>
#include <cuda_pipeline.h>
#include <math.h>

using namespace nvcuda;

// Problem dims
#define MROWS 16384            // B*S
#define DDIM  2048             // D
#define MSZ   ((size_t)MROWS * DDIM)
#define WSZ   ((size_t)DDIM * DDIM)

// ---------------- device scratch (allocation-free rule) ------------------------
__device__ __nv_bfloat16 g_Ah[MSZ];
__device__ __nv_bfloat16 g_Al[MSZ];
__device__ __nv_bfloat16 g_Hh[MSZ];
__device__ __nv_bfloat16 g_Hl[MSZ];
__device__ __nv_bfloat16 g_Wh[5 * WSZ];    // weight splits [K,N] row-major
__device__ __nv_bfloat16 g_Wl[5 * WSZ];
__device__ float g_Q [MSZ];
__device__ float g_K [MSZ];
__device__ float g_V [MSZ];
__device__ float g_X1[MSZ];

// ---------------- split fp32 -> (bf16 hi, bf16 lo) -----------------------------
__global__ void split_kernel(const float* __restrict__ x,
                             __nv_bfloat16* __restrict__ hi,
                             __nv_bfloat16* __restrict__ lo, int n)
{
    int i = blockIdx.x * blockDim.x + threadIdx.x;
    if (i < n) {
        float v = x[i];
        __nv_bfloat16 h = __float2bfloat16(v);
        hi[i] = h;
        lo[i] = __float2bfloat16(v - __bfloat162float(h));
    }
}

// ================= bf16x3 GEMM, HMMA path, L2-feed-optimized ===================
// C[M,N] = (Ah+Al)(Bh+Bl), fp32 accum. Logical K3 = 3*2048:
//   seg0 = Ah*Bh, seg1 = Al*Bh, seg2 = Ah*Bl   (AlBl dropped, ~2^-16 rel)
// CTA tile 128x256, BK=32, 3-stage cp.async, 8 warps of 64x64.
constexpr int BM = 128, BN = 256, BK = 32;
constexpr int NSTG = 3;
constexpr int APAD = 8,  LDA = BK + APAD;     // 40  (80B rows: conflict-free)
constexpr int BPAD = 8,  LDB = BN + BPAD;     // 264 (528B rows: conflict-free)
constexpr int A_BYTES = BM * LDA * 2;         // 10240
constexpr int B_BYTES = BK * LDB * 2;         // 16896
constexpr int STG_BYTES = A_BYTES + B_BYTES;  // 27136
constexpr int GEMM_SMEM = NSTG * STG_BYTES;   // 81408

template<int EPI>
__global__ void __launch_bounds__(256, 1)
gemm_bf16x3(const __nv_bfloat16* __restrict__ Ah, const __nv_bfloat16* __restrict__ Al,
            const __nv_bfloat16* __restrict__ Bh, const __nv_bfloat16* __restrict__ Bl,
            const float* __restrict__ bias,
            float* __restrict__ C,
            __nv_bfloat16* __restrict__ Oh, __nv_bfloat16* __restrict__ Ol)
{
    constexpr int K = DDIM, N = DDIM;
    extern __shared__ char dsm[];

    const int tid  = threadIdx.x;
    const int warp = tid >> 5, lane = tid & 31;
    const int wr = warp >> 2;          // 0..1 -> 64-row slab
    const int wc = warp & 3;           // 0..3 -> 64-col slab
    const int m0 = blockIdx.y * BM, n0 = blockIdx.x * BN;

    wmma::fragment<wmma::accumulator, 16, 16, 16, float> acc[4][4];
    #pragma unroll
    for (int i = 0; i < 4; i++)
        #pragma unroll
        for (int j = 0; j < 4; j++) wmma::fill_fragment(acc[i][j], 0.0f);

    auto load_stage = [&](int s, int kt) {
        int seg = (kt >= 2 * K) ? 2 : ((kt >= K) ? 1 : 0);
        int kk  = kt - seg * K;
        const __nv_bfloat16* Ap = (seg == 1) ? Al : Ah;
        const __nv_bfloat16* Bp = (seg == 2) ? Bl : Bh;
        __nv_bfloat16* sA = (__nv_bfloat16*)(dsm + s * STG_BYTES);
        __nv_bfloat16* sB = (__nv_bfloat16*)(dsm + s * STG_BYTES + A_BYTES);
        #pragma unroll
        for (int r = 0; r < 2; r++) {              // A: 128x32 = 512 x 16B
            int idx = tid + r * 256;
            int row = idx >> 2, c8 = (idx & 3) * 8;
            __pipeline_memcpy_async(sA + row * LDA + c8,
                                    Ap + (size_t)(m0 + row) * K + kk + c8, 16);
        }
        #pragma unroll
        for (int r = 0; r < 4; r++) {              // B: 32x256 = 1024 x 16B
            int idx = tid + r * 256;
            int row = idx >> 5, c8 = (idx & 31) * 8;
            __pipeline_memcpy_async(sB + row * LDB + c8,
                                    Bp + (size_t)(kk + row) * N + n0 + c8, 16);
        }
    };

    const int nIter = (3 * K) / BK;   // 192
    load_stage(0, 0);             __pipeline_commit();
    load_stage(1, BK);            __pipeline_commit();

    for (int it = 0; it < nIter; ++it) {
        int cur = it % NSTG;
        __pipeline_wait_prior(1);          // stage `it` resident
        __syncthreads();                   // + prev compute done before overwrite
        if (it + 2 < nIter) load_stage((it + 2) % NSTG, (it + 2) * BK);
        __pipeline_commit();               // always commit (keeps group counts aligned)

        const __nv_bfloat16* sA = (const __nv_bfloat16*)(dsm + cur * STG_BYTES);
        const __nv_bfloat16* sB = (const __nv_bfloat16*)(dsm + cur * STG_BYTES + A_BYTES);
        #pragma unroll
        for (int k2 = 0; k2 < BK; k2 += 16) {
            wmma::fragment<wmma::matrix_a, 16, 16, 16, __nv_bfloat16, wmma::row_major> af[4];
            wmma::fragment<wmma::matrix_b, 16, 16, 16, __nv_bfloat16, wmma::row_major> bf[4];
            #pragma unroll
            for (int i = 0; i < 4; i++)
                wmma::load_matrix_sync(af[i], sA + (wr * 64 + i * 16) * LDA + k2, LDA);
            #pragma unroll
            for (int j = 0; j < 4; j++)
                wmma::load_matrix_sync(bf[j], sB + k2 * LDB + wc * 64 + j * 16, LDB);
            #pragma unroll
            for (int i = 0; i < 4; i++)
                #pragma unroll
                for (int j = 0; j < 4; j++)
                    wmma::mma_sync(acc[i][j], af[i], bf[j], acc[i][j]);
        }
    }
    __syncthreads();

    // epilogue: per-warp smem staging, coalesced stores
    float* buf = (float*)dsm + warp * 272;
    #pragma unroll
    for (int i = 0; i < 4; i++) {
        #pragma unroll
        for (int j = 0; j < 4; j++) {
            wmma::store_matrix_sync(buf, acc[i][j], 16, wmma::mem_row_major);
            __syncwarp();
            const int gr = m0 + wr * 64 + i * 16;
            const int gc = n0 + wc * 64 + j * 16;
            const int r  = lane >> 1, ch = (lane & 1) * 8;
            #pragma unroll
            for (int e = 0; e < 8; e++) {
                int cc = ch + e;
                float v = buf[r * 16 + cc] + bias[gc + cc];
                size_t o = (size_t)(gr + r) * N + gc + cc;
                if (EPI == 0) {
                    C[o] = v;
                } else {
                    float gl = v * normcdff(v);            // exact GELU
                    __nv_bfloat16 hh = __float2bfloat16(gl);
                    Oh[o] = hh;
                    Ol[o] = __float2bfloat16(gl - __bfloat162float(hh));
                }
            }
            __syncwarp();
        }
    }
}

// ---------------- per-token head-attention + residual + LN1 --------------------
__global__ void __launch_bounds__(128)
attn_ln1_kernel(const float* __restrict__ Q, const float* __restrict__ Kk,
                const float* __restrict__ V, const float* __restrict__ X,
                const float* __restrict__ g1, const float* __restrict__ be1,
                float* __restrict__ X1,
                __nv_bfloat16* __restrict__ Oh, __nv_bfloat16* __restrict__ Ol)
{
    __shared__ float sq[16 * 129], sk[16 * 129], sv[16 * 129];
    __shared__ float satt[16][16];
    __shared__ float red[8];
    const int t = blockIdx.x, tid = threadIdx.x;
    const size_t base = (size_t)t * DDIM;
    for (int i = tid; i < DDIM; i += 128) {
        int h = i >> 7, d = i & 127, o = h * 129 + d;
        sq[o] = Q[base + i]; sk[o] = Kk[base + i]; sv[o] = V[base + i];
    }
    __syncthreads();
    for (int p = tid; p < 256; p += 128) {
        int h = p >> 4, tt = p & 15;
        const float* qp = sq + h * 129;
        const float* kp = sk + tt * 129;
        float s = 0.f;
        #pragma unroll
        for (int d = 0; d < 128; d++) s += qp[d] * kp[d];
        satt[h][tt] = s * 0.08838834764831845f;
    }
    __syncthreads();
    if (tid < 16) {
        float mx = -1e30f;
        #pragma unroll
        for (int j = 0; j < 16; j++) mx = fmaxf(mx, satt[tid][j]);
        float sum = 0.f;
        #pragma unroll
        for (int j = 0; j < 16; j++) { float e = expf(satt[tid][j] - mx); satt[tid][j] = e; sum += e; }
        float inv = 1.f / sum;
        #pragma unroll
        for (int j = 0; j < 16; j++) satt[tid][j] *= inv;
    }
    __syncthreads();
    float xp[16], ls = 0.f, lq = 0.f;
    #pragma unroll
    for (int i = 0; i < 16; i++) {
        int o = tid + i * 128, h = o >> 7, d = o & 127;
        float y = 0.f;
        #pragma unroll
        for (int tt = 0; tt < 16; tt++) y += satt[h][tt] * sv[tt * 129 + d];
        float xv = X[base + o] + y;
        xp[i] = xv; ls += xv; lq += xv * xv;
    }
    #pragma unroll
    for (int off = 16; off; off >>= 1) {
        ls += __shfl_xor_sync(0xffffffffu, ls, off);
        lq += __shfl_xor_sync(0xffffffffu, lq, off);
    }
    if ((tid & 31) == 0) { red[tid >> 5] = ls; red[4 + (tid >> 5)] = lq; }
    __syncthreads();
    float S  = red[0] + red[1] + red[2] + red[3];
    float Qs = red[4] + red[5] + red[6] + red[7];
    float mean = S * (1.0f / DDIM);
    float var  = Qs * (1.0f / DDIM) - mean * mean;
    float inv  = rsqrtf(var + 1e-5f);
    #pragma unroll
    for (int i = 0; i < 16; i++) {
        int o = tid + i * 128;
        float v = (xp[i] - mean) * inv * g1[o] + be1[o];
        X1[base + o] = v;
        __nv_bfloat16 hh = __float2bfloat16(v);
        Oh[base + o] = hh;
        Ol[base + o] = __float2bfloat16(v - __bfloat162float(hh));
    }
}

// ---------------- out = LN(A + B) * g + beta -----------------------------------
__global__ void __launch_bounds__(256)
add_ln_kernel(const float* __restrict__ A, const float* __restrict__ Bv,
              const float* __restrict__ g, const float* __restrict__ be,
              float* __restrict__ out)
{
    __shared__ float red[16];
    const int t = blockIdx.x, tid = threadIdx.x;
    const size_t base = (size_t)t * DDIM;
    float xp[8], ls = 0.f, lq = 0.f;
    #pragma unroll
    for (int i = 0; i < 8; i++) {
        int o = tid + i * 256;
        float xv = A[base + o] + Bv[base + o];
        xp[i] = xv; ls += xv; lq += xv * xv;
    }
    #pragma unroll
    for (int off = 16; off; off >>= 1) {
        ls += __shfl_xor_sync(0xffffffffu, ls, off);
        lq += __shfl_xor_sync(0xffffffffu, lq, off);
    }
    if ((tid & 31) == 0) { red[tid >> 5] = ls; red[8 + (tid >> 5)] = lq; }
    __syncthreads();
    float S = 0.f, Qs = 0.f;
    #pragma unroll
    for (int w = 0; w < 8; w++) { S += red[w]; Qs += red[8 + w]; }
    float mean = S * (1.0f / DDIM);
    float var  = Qs * (1.0f / DDIM) - mean * mean;
    float inv  = rsqrtf(var + 1e-5f);
    #pragma unroll
    for (int i = 0; i < 8; i++) {
        int o = tid + i * 256;
        out[base + o] = (xp[i] - mean) * inv * g[o] + be[o];
    }
}

// ---------------- host orchestration -------------------------------------------
extern "C" void kernel_launch(void* const* d_in, const int* in_sizes, int n_in,
                              void* d_out, int out_size)
{
    const float* X     = (const float*)d_in[0];
    const float* Wq    = (const float*)d_in[1];
    const float* bq    = (const float*)d_in[2];
    const float* Wk    = (const float*)d_in[3];
    const float* bk    = (const float*)d_in[4];
    const float* Wv    = (const float*)d_in[5];
    const float* bv    = (const float*)d_in[6];
    const float* g1    = (const float*)d_in[7];
    const float* beta1 = (const float*)d_in[8];
    const float* W1    = (const float*)d_in[9];
    const float* b1    = (const float*)d_in[10];
    const float* W2    = (const float*)d_in[11];
    const float* b2    = (const float*)d_in[12];
    const float* g2    = (const float*)d_in[13];
    const float* beta2 = (const float*)d_in[14];
    float* out = (float*)d_out;

    __nv_bfloat16 *Ah, *Al, *Hh, *Hl, *Wh, *Wl;
    float *Q, *K, *V, *X1;
    cudaGetSymbolAddress((void**)&Ah, g_Ah);
    cudaGetSymbolAddress((void**)&Al, g_Al);
    cudaGetSymbolAddress((void**)&Hh, g_Hh);
    cudaGetSymbolAddress((void**)&Hl, g_Hl);
    cudaGetSymbolAddress((void**)&Wh, g_Wh);
    cudaGetSymbolAddress((void**)&Wl, g_Wl);
    cudaGetSymbolAddress((void**)&Q,  g_Q);
    cudaGetSymbolAddress((void**)&K,  g_K);
    cudaGetSymbolAddress((void**)&V,  g_V);
    cudaGetSymbolAddress((void**)&X1, g_X1);

    cudaFuncSetAttribute(gemm_bf16x3<0>, cudaFuncAttributeMaxDynamicSharedMemorySize, GEMM_SMEM);
    cudaFuncSetAttribute(gemm_bf16x3<1>, cudaFuncAttributeMaxDynamicSharedMemorySize, GEMM_SMEM);

    const int nA = MROWS * DDIM, nW = DDIM * DDIM;
    split_kernel<<<(nA + 255) / 256, 256>>>(X,  Ah, Al, nA);
    split_kernel<<<(nW + 255) / 256, 256>>>(Wq, Wh + 0 * WSZ, Wl + 0 * WSZ, nW);
    split_kernel<<<(nW + 255) / 256, 256>>>(Wk, Wh + 1 * WSZ, Wl + 1 * WSZ, nW);
    split_kernel<<<(nW + 255) / 256, 256>>>(Wv, Wh + 2 * WSZ, Wl + 2 * WSZ, nW);
    split_kernel<<<(nW + 255) / 256, 256>>>(W1, Wh + 3 * WSZ, Wl + 3 * WSZ, nW);
    split_kernel<<<(nW + 255) / 256, 256>>>(W2, Wh + 4 * WSZ, Wl + 4 * WSZ, nW);

    dim3 gg(DDIM / BN, MROWS / BM);   // (8, 128)
    gemm_bf16x3<0><<<gg, 256, GEMM_SMEM>>>(Ah, Al, Wh + 0 * WSZ, Wl + 0 * WSZ, bq, Q,  nullptr, nullptr);
    gemm_bf16x3<0><<<gg, 256, GEMM_SMEM>>>(Ah, Al, Wh + 1 * WSZ, Wl + 1 * WSZ, bk, K,  nullptr, nullptr);
    gemm_bf16x3<0><<<gg, 256, GEMM_SMEM>>>(Ah, Al, Wh + 2 * WSZ, Wl + 2 * WSZ, bv, V,  nullptr, nullptr);

    attn_ln1_kernel<<<MROWS, 128>>>(Q, K, V, X, g1, beta1, X1, Ah, Al);

    gemm_bf16x3<1><<<gg, 256, GEMM_SMEM>>>(Ah, Al, Wh + 3 * WSZ, Wl + 3 * WSZ, b1, nullptr, Hh, Hl);
    gemm_bf16x3<0><<<gg, 256, GEMM_SMEM>>>(Hh, Hl, Wh + 4 * WSZ, Wl + 4 * WSZ, b2, Q,  nullptr, nullptr);

    add_ln_kernel<<<MROWS, 256>>>(X1, Q, g2, beta2, out);
}